// round 5
// baseline (speedup 1.0000x reference)
#include <cuda_runtime.h>
#include <math.h>

#define S_ 64
#define B_ 32
#define H_ 1024
#define E_ 512
#define V_ 32000
#define HB (H_*B_)          // 32768
#define KSPLIT 8

// ---------------- device scratch (no allocs allowed) ----------------
__device__ float g_xT[S_*E_*B_];        // [t][e][b]
__device__ float g_h0T[(S_+1)*HB];      // [slot][i][b]
__device__ float g_h1T[(S_+1)*HB];      // [slot][i][b]
__device__ float g_tops[S_*B_*H_];      // [t][b][i]
__device__ float g_partA[KSPLIT*HB];    // layer0 k-split partials
__device__ float g_partB[KSPLIT*HB];    // layer1 k-split partials
__device__ unsigned g_cnt[32];          // arrival counters (zero-init; winner resets)

// ---------------- packed f32x2 fma ----------------------------------
__device__ __forceinline__ unsigned long long ffma2(unsigned long long a,
                                                    unsigned long long b,
                                                    unsigned long long c) {
    unsigned long long d;
    asm("fma.rn.f32x2 %0, %1, %2, %3;" : "=l"(d) : "l"(a), "l"(b), "l"(c));
    return d;
}
__device__ __forceinline__ float2 up2(unsigned long long v) {
    float2 r;
    r.x = __uint_as_float((unsigned)v);
    r.y = __uint_as_float((unsigned)(v >> 32));
    return r;
}

// ---------------- init: transpose initial hidden --------------------
__global__ void init_hidden_k(const float* __restrict__ hidden) {
    int idx = blockIdx.x * blockDim.x + threadIdx.x;
    if (idx >= 2*B_*H_) return;
    int l = idx >> 15;
    int rem = idx & 32767;
    int b = rem >> 10;
    int i = rem & 1023;
    float v = hidden[idx];
    float* dst = l ? g_h1T : g_h0T;
    dst[i*B_ + b] = v;
}

// ---------------- embedding gather: xT[t][e][b] ----------------------
__global__ void embed_all_k(const int* __restrict__ tok, const float* __restrict__ emb) {
    int idx = blockIdx.x * blockDim.x + threadIdx.x;
    if (idx >= S_*E_*B_) return;
    int b = idx & 31;
    int e = (idx >> 5) & 511;
    int t = idx >> 14;
    int tk = tok[t*B_ + b];
    g_xT[idx] = emb[(size_t)tk * E_ + e];
}

// ---------------- fused pipelined wave kernel ------------------------
// blocks 0..127:   layer0 step w   (if actA)
// blocks 128..255: layer1 step w-1 (if actB)
// Each (itile,kseg) block computes a 64i x 32b k-split partial; the last
// arriving block per (layer,itile) sums the 8 partials in fixed order,
// adds bias, applies tanh, writes the new hidden state (and tops for L1).
#define KC 32
__global__ void rnn_wave(
    const float* __restrict__ Wx0, const float* __restrict__ Wh0, const float* __restrict__ bh0,
    const float* __restrict__ Wx1, const float* __restrict__ Wh1, const float* __restrict__ bh1,
    const float* __restrict__ aA, const float* __restrict__ hA, float* __restrict__ outA,
    const float* __restrict__ aB, const float* __restrict__ hB, float* __restrict__ outB,
    float* __restrict__ topsB, int actA, int actB)
{
    int blk = blockIdx.x;
    int isB = blk >> 7;
    if (isB ? !actB : !actA) return;
    int lb = blk & 127;
    int itile = lb & 15;
    int kseg = lb >> 4;

    const float* Wx   = isB ? Wx1 : Wx0;
    const float* Wh   = isB ? Wh1 : Wh0;
    const float* bias = isB ? bh1 : bh0;
    const float* aT   = isB ? aB  : aA;
    const float* hT   = isB ? hB  : hA;
    float* outT = isB ? outB : outA;
    float* part = isB ? g_partB : g_partA;
    int KA = isB ? H_ : E_;
    int seglen = (KA + H_) / KSPLIT;   // 256 or 192

    __shared__ float Ws[64][33];
    __shared__ float As[KC][32];
    int tid = threadIdx.x;
    int bq = tid & 7;
    int iq = tid >> 3;
    int i0 = itile * 64;
    int k0 = kseg * seglen;

    float acc[4][4];
#pragma unroll
    for (int j = 0; j < 4; j++)
#pragma unroll
        for (int bb = 0; bb < 4; bb++) acc[j][bb] = 0.f;

    for (int kb = k0; kb < k0 + seglen; kb += KC) {
        bool isx = (kb < KA);
        const float* Wp = isx ? (Wx + (size_t)i0 * KA + kb)
                              : (Wh + (size_t)i0 * H_ + (kb - KA));
        int ldw = isx ? KA : H_;
        const float* ap = isx ? (aT + (size_t)kb * B_)
                              : (hT + (size_t)(kb - KA) * B_);
#pragma unroll
        for (int q = 0; q < 4; q++) {
            int f = tid + 128 * q;
            int r = f >> 3;
            int c4 = (f & 7) << 2;
            float4 w4 = *(const float4*)(Wp + (size_t)r * ldw + c4);
            Ws[r][c4 + 0] = w4.x; Ws[r][c4 + 1] = w4.y;
            Ws[r][c4 + 2] = w4.z; Ws[r][c4 + 3] = w4.w;
        }
#pragma unroll
        for (int q = 0; q < 2; q++) {
            int f = tid + 128 * q;
            ((float4*)As)[f] = ((const float4*)ap)[f];
        }
        __syncthreads();
#pragma unroll
        for (int k = 0; k < KC; k++) {
            float4 a4 = *(const float4*)&As[k][bq << 2];
#pragma unroll
            for (int j = 0; j < 4; j++) {
                float w = Ws[iq * 4 + j][k];
                acc[j][0] += w * a4.x;
                acc[j][1] += w * a4.y;
                acc[j][2] += w * a4.z;
                acc[j][3] += w * a4.w;
            }
        }
        __syncthreads();
    }
    float* pp = part + (size_t)kseg * HB;
#pragma unroll
    for (int j = 0; j < 4; j++) {
        int i = i0 + iq * 4 + j;
        float4 v = make_float4(acc[j][0], acc[j][1], acc[j][2], acc[j][3]);
        *(float4*)(pp + (size_t)i * B_ + (bq << 2)) = v;
    }

    // ---- last-block fused reduction + tanh ----
    __threadfence();
    __syncthreads();
    __shared__ int swin;
    int ci = isB * 16 + itile;
    if (tid == 0) {
        unsigned old = atomicAdd(&g_cnt[ci], 1u);
        swin = (old == KSPLIT - 1);
    }
    __syncthreads();
    if (!swin) return;
    __threadfence();

    float* tops = isB ? topsB : (float*)0;
#pragma unroll
    for (int j = 0; j < 16; j++) {
        int idx = tid + j * 128;            // 0..2047 within tile
        int il = idx >> 5;
        int b  = idx & 31;
        int gi = i0 + il;
        float s = bias[gi];
#pragma unroll
        for (int ks = 0; ks < KSPLIT; ks++)
            s += __ldcg(&part[(size_t)ks * HB + (size_t)gi * B_ + b]);
        float v = tanhf(s);
        outT[(size_t)gi * B_ + b] = v;
        if (tops) tops[(size_t)b * H_ + gi] = v;
    }
    __syncthreads();
    if (tid == 0) g_cnt[ci] = 0;            // rearm for next wave
}

// ---------------- output projection SGEMM (f32x2 packed) --------------
// C[m][n] = A[m][:H] . Bw[n][:H] + bout[n]
#define BM 64
#define BN 128
#define BK 16
__global__ void out_gemm(const float* __restrict__ A, const float* __restrict__ Bw,
                         const float* __restrict__ bout, float* __restrict__ C) {
    __shared__ float As2[BK][2*BM + 8];   // A duplicated: [k][2m]=[k][2m+1]=a, stride 136 (544B)
    __shared__ float Bs[BK][BN + 4];      // stride 132 (528B)
    int tid = threadIdx.x;
    int tx = tid & 15;        // n group: 8 cols (4 + 4 at +64)
    int ty = tid >> 4;        // m group: 4 rows
    int m0 = blockIdx.y * BM;
    int n0 = blockIdx.x * BN;

    unsigned long long acc[4][4];         // [m][n-pair]
#pragma unroll
    for (int a = 0; a < 4; a++)
#pragma unroll
        for (int b = 0; b < 4; b++) acc[a][b] = 0ull;

    int la_m = tid >> 2;            // 0..63
    int la_k = (tid & 3) << 2;      // 0,4,8,12

    for (int kb = 0; kb < H_; kb += BK) {
        float4 a4 = *(const float4*)(A + (size_t)(m0 + la_m) * H_ + kb + la_k);
        *(float2*)&As2[la_k + 0][2*la_m] = make_float2(a4.x, a4.x);
        *(float2*)&As2[la_k + 1][2*la_m] = make_float2(a4.y, a4.y);
        *(float2*)&As2[la_k + 2][2*la_m] = make_float2(a4.z, a4.z);
        *(float2*)&As2[la_k + 3][2*la_m] = make_float2(a4.w, a4.w);
        float4 b4 = *(const float4*)(Bw + (size_t)(n0 + la_m) * H_ + kb + la_k);
        Bs[la_k + 0][la_m] = b4.x; Bs[la_k + 1][la_m] = b4.y;
        Bs[la_k + 2][la_m] = b4.z; Bs[la_k + 3][la_m] = b4.w;
        float4 b5 = *(const float4*)(Bw + (size_t)(n0 + la_m + 64) * H_ + kb + la_k);
        Bs[la_k + 0][la_m + 64] = b5.x; Bs[la_k + 1][la_m + 64] = b5.y;
        Bs[la_k + 2][la_m + 64] = b5.z; Bs[la_k + 3][la_m + 64] = b5.w;
        __syncthreads();
#pragma unroll
        for (int kk = 0; kk < BK; kk++) {
            ulonglong2 ap0 = *(const ulonglong2*)&As2[kk][ty << 3];        // (a0a0),(a1a1)
            ulonglong2 ap1 = *(const ulonglong2*)&As2[kk][(ty << 3) + 4];  // (a2a2),(a3a3)
            ulonglong2 bp0 = *(const ulonglong2*)&Bs[kk][tx << 2];         // (b0,b1),(b2,b3)
            ulonglong2 bp1 = *(const ulonglong2*)&Bs[kk][(tx << 2) + 64];  // (b4,b5),(b6,b7)
            unsigned long long am[4] = {ap0.x, ap0.y, ap1.x, ap1.y};
            unsigned long long bn[4] = {bp0.x, bp0.y, bp1.x, bp1.y};
#pragma unroll
            for (int a = 0; a < 4; a++)
#pragma unroll
                for (int b = 0; b < 4; b++)
                    acc[a][b] = ffma2(am[a], bn[b], acc[a][b]);
        }
        __syncthreads();
    }

    int n = n0 + (tx << 2);
    float bo0 = bout[n + 0], bo1 = bout[n + 1], bo2 = bout[n + 2], bo3 = bout[n + 3];
    float bo4 = bout[n + 64], bo5 = bout[n + 65], bo6 = bout[n + 66], bo7 = bout[n + 67];
#pragma unroll
    for (int mm = 0; mm < 4; mm++) {
        size_t row = (size_t)(m0 + (ty << 2) + mm) * V_;
        float2 u0 = up2(acc[mm][0]), u1 = up2(acc[mm][1]);
        float2 u2 = up2(acc[mm][2]), u3 = up2(acc[mm][3]);
        float4 r0 = make_float4(u0.x + bo0, u0.y + bo1, u1.x + bo2, u1.y + bo3);
        float4 r1 = make_float4(u2.x + bo4, u2.y + bo5, u3.x + bo6, u3.y + bo7);
        *(float4*)(C + row + n)      = r0;
        *(float4*)(C + row + n + 64) = r1;
    }
}

// ---------------- hidden_final writeback ------------------------------
__global__ void finalize_k(float* __restrict__ outTail) {
    int idx = blockIdx.x * blockDim.x + threadIdx.x;
    if (idx >= 2*B_*H_) return;
    int l = idx >> 15;
    int rem = idx & 32767;
    int b = rem >> 10;
    int i = rem & 1023;
    const float* src = (l ? g_h1T : g_h0T) + (size_t)S_ * HB;
    outTail[idx] = src[i*B_ + b];
}

// ---------------- launch ---------------------------------------------
extern "C" void kernel_launch(void* const* d_in, const int* in_sizes, int n_in,
                              void* d_out, int out_size) {
    const int*   tok   = (const int*)  d_in[0];
    const float* hidden= (const float*)d_in[1];
    const float* emb   = (const float*)d_in[2];
    const float* Wx0   = (const float*)d_in[3];
    const float* Wh0   = (const float*)d_in[4];
    const float* bh0   = (const float*)d_in[5];
    const float* Wx1   = (const float*)d_in[6];
    const float* Wh1   = (const float*)d_in[7];
    const float* bh1   = (const float*)d_in[8];
    const float* Wout  = (const float*)d_in[9];
    const float* bout  = (const float*)d_in[10];
    float* out = (float*)d_out;

    float *xT, *h0T, *h1T, *tops;
    cudaGetSymbolAddress((void**)&xT,   g_xT);
    cudaGetSymbolAddress((void**)&h0T,  g_h0T);
    cudaGetSymbolAddress((void**)&h1T,  g_h1T);
    cudaGetSymbolAddress((void**)&tops, g_tops);

    init_hidden_k<<<(2*B_*H_ + 255)/256, 256>>>(hidden);
    embed_all_k<<<(S_*E_*B_ + 255)/256, 256>>>(tok, emb);

    for (int w = 0; w <= S_; w++) {
        int wa = (w < S_) ? w : (S_ - 1);       // clamp (inactive side unused)
        int wb = (w >= 1) ? w : 1;
        const float* aA = xT  + (size_t)wa * E_ * B_;
        const float* hA = h0T + (size_t)wa * HB;
        float*       oA = h0T + (size_t)(wa + 1) * HB;
        const float* aB = h0T + (size_t)wb * HB;          // layer0 output of step wb-1
        const float* hB = h1T + (size_t)(wb - 1) * HB;
        float*       oB = h1T + (size_t)wb * HB;
        float*       tB = tops + (size_t)(wb - 1) * B_ * H_;
        rnn_wave<<<256, 128>>>(Wx0, Wh0, bh0, Wx1, Wh1, bh1,
                               aA, hA, oA, aB, hB, oB, tB,
                               (w < S_) ? 1 : 0, (w >= 1) ? 1 : 0);
    }

    out_gemm<<<dim3(V_/BN, (S_*B_)/BM), 256>>>(tops, Wout, bout, out);
    finalize_k<<<(2*B_*H_ + 255)/256, 256>>>(out + (size_t)S_*B_*V_);
}